// round 1
// baseline (speedup 1.0000x reference)
#include <cuda_runtime.h>
#include <math.h>

// Problem dimensions (fixed by the reference)
#define BATCH 8192
#define PDIM  512
#define H1DIM 1024
#define H2DIM 512
#define NOUTD 1024
#define MMDIM 512
#define NCODE 2048
#define KSTEPS 16

// ---------------- scratch (device globals; no allocations allowed) ----------
__device__ float g_h1[(size_t)BATCH * H1DIM];        // MLP hidden 1
__device__ float g_h2[(size_t)BATCH * H2DIM];        // MLP hidden 2, reused as r [B, Mm]
__device__ float g_v [(size_t)BATCH * NCODE];        // FISTA extrapolation point
__device__ float g_a0[(size_t)BATCH * NCODE];        // alpha ping
__device__ float g_a1[(size_t)BATCH * NCODE];        // alpha pong

enum { EPI_GELU = 0, EPI_BIAS, EPI_ZSUB, EPI_RSUB, EPI_FISTA, EPI_ADD };

__device__ __forceinline__ float gelu_exact(float x) {
    // jax.nn.gelu(approximate=False) = 0.5*x*(1+erf(x/sqrt(2)))
    return 0.5f * x * (1.0f + erff(x * 0.70710678118654752440f));
}

// ---------------------------------------------------------------------------
// Tiled fp32 GEMM: C[M,N] = A[M,K] * B, 128x128 tile, BK=16, 256 threads,
// double-buffered SMEM, 8x8 per-thread microtile. BT=false: B is [K,N]
// row-major.  BT=true: B is [N,K] row-major (i.e. compute A*B^T).
// M, N multiples of 128; K multiple of 16 (guaranteed by problem shapes).
// ---------------------------------------------------------------------------
template <int EPI, bool BT>
__global__ void __launch_bounds__(256)
gemm128(const float* __restrict__ Ag, const float* __restrict__ Bg,
        float* __restrict__ Cg, int Ndim, int Kdim,
        const float* __restrict__ aux,        // bias [N] or matrix [M,N] per EPI
        const float* __restrict__ log_eta,
        const float* __restrict__ log_tau, int kidx)
{
    __shared__ float As[2][16][128];
    __shared__ float Bs[2][16][128];

    const int tid = threadIdx.x;
    const int tx  = tid & 15;     // 0..15 : 8-col group
    const int ty  = tid >> 4;     // 0..15 : 8-row group
    const int m0  = blockIdx.y * 128;
    const int n0  = blockIdx.x * 128;

    // loader indices
    const int lr = tid >> 2;      // 0..63  (row, A and B-NT)
    const int lc = tid & 3;       // 0..3   (float4 slot along K)
    const int br = tid >> 5;      // 0..7   (k-row, B-NN)
    const int bc = tid & 31;      // 0..31  (float4 slot along N)

    float acc[8][8];
#pragma unroll
    for (int i = 0; i < 8; i++)
#pragma unroll
        for (int j = 0; j < 8; j++) acc[i][j] = 0.0f;

    const int nk = Kdim >> 4;

    // ---- preload tile 0 -----------------------------------------------------
    {
        float4 a0 = *(const float4*)&Ag[(size_t)(m0 + lr) * Kdim + lc * 4];
        float4 a1 = *(const float4*)&Ag[(size_t)(m0 + lr + 64) * Kdim + lc * 4];
#pragma unroll
        for (int j = 0; j < 4; j++) {
            As[0][lc * 4 + j][lr]      = ((const float*)&a0)[j];
            As[0][lc * 4 + j][lr + 64] = ((const float*)&a1)[j];
        }
        if (BT) {
            float4 b0 = *(const float4*)&Bg[(size_t)(n0 + lr) * Kdim + lc * 4];
            float4 b1 = *(const float4*)&Bg[(size_t)(n0 + lr + 64) * Kdim + lc * 4];
#pragma unroll
            for (int j = 0; j < 4; j++) {
                Bs[0][lc * 4 + j][lr]      = ((const float*)&b0)[j];
                Bs[0][lc * 4 + j][lr + 64] = ((const float*)&b1)[j];
            }
        } else {
            float4 b0 = *(const float4*)&Bg[(size_t)br * Ndim + n0 + bc * 4];
            float4 b1 = *(const float4*)&Bg[(size_t)(br + 8) * Ndim + n0 + bc * 4];
            *(float4*)&Bs[0][br][bc * 4]     = b0;
            *(float4*)&Bs[0][br + 8][bc * 4] = b1;
        }
    }
    __syncthreads();

    int buf = 0;
    for (int kt = 0; kt < nk; kt++) {
        float4 pa0, pa1, pb0, pb1;
        const bool more = (kt + 1 < nk);
        if (more) {   // issue next-tile global loads early; latency hides under FMAs
            const int ko = (kt + 1) * 16;
            pa0 = *(const float4*)&Ag[(size_t)(m0 + lr) * Kdim + ko + lc * 4];
            pa1 = *(const float4*)&Ag[(size_t)(m0 + lr + 64) * Kdim + ko + lc * 4];
            if (BT) {
                pb0 = *(const float4*)&Bg[(size_t)(n0 + lr) * Kdim + ko + lc * 4];
                pb1 = *(const float4*)&Bg[(size_t)(n0 + lr + 64) * Kdim + ko + lc * 4];
            } else {
                pb0 = *(const float4*)&Bg[(size_t)(ko + br) * Ndim + n0 + bc * 4];
                pb1 = *(const float4*)&Bg[(size_t)(ko + br + 8) * Ndim + n0 + bc * 4];
            }
        }
#pragma unroll
        for (int k = 0; k < 16; k++) {
            float4 av0 = *(const float4*)&As[buf][k][ty * 8];
            float4 av1 = *(const float4*)&As[buf][k][ty * 8 + 4];
            float4 bv0 = *(const float4*)&Bs[buf][k][tx * 8];
            float4 bv1 = *(const float4*)&Bs[buf][k][tx * 8 + 4];
            float a[8] = {av0.x, av0.y, av0.z, av0.w, av1.x, av1.y, av1.z, av1.w};
            float b[8] = {bv0.x, bv0.y, bv0.z, bv0.w, bv1.x, bv1.y, bv1.z, bv1.w};
#pragma unroll
            for (int i = 0; i < 8; i++)
#pragma unroll
                for (int j = 0; j < 8; j++)
                    acc[i][j] = fmaf(a[i], b[j], acc[i][j]);
        }
        if (more) {
            const int nb = buf ^ 1;
#pragma unroll
            for (int j = 0; j < 4; j++) {
                As[nb][lc * 4 + j][lr]      = ((const float*)&pa0)[j];
                As[nb][lc * 4 + j][lr + 64] = ((const float*)&pa1)[j];
            }
            if (BT) {
#pragma unroll
                for (int j = 0; j < 4; j++) {
                    Bs[nb][lc * 4 + j][lr]      = ((const float*)&pb0)[j];
                    Bs[nb][lc * 4 + j][lr + 64] = ((const float*)&pb1)[j];
                }
            } else {
                *(float4*)&Bs[nb][br][bc * 4]     = pb0;
                *(float4*)&Bs[nb][br + 8][bc * 4] = pb1;
            }
            __syncthreads();
            buf = nb;
        }
    }

    // ---- fused epilogue -----------------------------------------------------
    float eta = 0.0f, thr = 0.0f;
    if (EPI == EPI_FISTA) {
        eta = expf(log_eta[kidx]);
        eta = fminf(fmaxf(eta, 1e-8f), 10.0f);
        float tau = expf(log_tau[kidx]);
        tau = fminf(fmaxf(tau, 1e-8f), 10.0f);
        thr = eta * tau;
    }
    const int cm = m0 + ty * 8;
    const int cn = n0 + tx * 8;
#pragma unroll
    for (int i = 0; i < 8; i++) {
#pragma unroll
        for (int j = 0; j < 8; j++) {
            float r = acc[i][j];
            float o;
            if (EPI == EPI_GELU) {
                o = gelu_exact(r + aux[cn + j]);
            } else if (EPI == EPI_BIAS) {
                o = r + aux[cn + j];
            } else if (EPI == EPI_ZSUB) {            // z = b - acc
                o = aux[(size_t)(cm + i) * Ndim + cn + j] - r;
            } else if (EPI == EPI_RSUB) {            // r = acc - z
                o = r - aux[(size_t)(cm + i) * Ndim + cn + j];
            } else if (EPI == EPI_FISTA) {           // soft(v - eta*acc, eta*tau)
                float u = aux[(size_t)(cm + i) * Ndim + cn + j] - eta * r;
                o = copysignf(fmaxf(fabsf(u) - thr, 0.0f), u);
            } else {                                 // EPI_ADD: y_hat = y_bg + acc
                o = r + aux[(size_t)(cm + i) * Ndim + cn + j];
            }
            acc[i][j] = o;
        }
        *(float4*)&Cg[(size_t)(cm + i) * Ndim + cn]     = *(float4*)&acc[i][0];
        *(float4*)&Cg[(size_t)(cm + i) * Ndim + cn + 4] = *(float4*)&acc[i][4];
    }
}

// v = alpha + beta*(alpha - alpha_prev), vectorized
__global__ void vcomb_kernel(const float4* __restrict__ a,
                             const float4* __restrict__ ap,
                             float4* __restrict__ v, float beta, int n4)
{
    int i = blockIdx.x * blockDim.x + threadIdx.x;
    if (i < n4) {
        float4 av = a[i], pv = ap[i], o;
        o.x = av.x + beta * (av.x - pv.x);
        o.y = av.y + beta * (av.y - pv.y);
        o.z = av.z + beta * (av.z - pv.z);
        o.w = av.w + beta * (av.w - pv.w);
        v[i] = o;
    }
}

__global__ void fill0_kernel(float4* __restrict__ p, int n4)
{
    int i = blockIdx.x * blockDim.x + threadIdx.x;
    if (i < n4) p[i] = make_float4(0.f, 0.f, 0.f, 0.f);
}

// ---------------------------------------------------------------------------
extern "C" void kernel_launch(void* const* d_in, const int* in_sizes, int n_in,
                              void* d_out, int out_size)
{
    const float* x    = (const float*)d_in[0];
    const float* bvec = (const float*)d_in[1];   // b  [B, Mm]
    const float* W1   = (const float*)d_in[2];
    const float* b1   = (const float*)d_in[3];
    const float* W2   = (const float*)d_in[4];
    const float* b2   = (const float*)d_in[5];
    const float* W3   = (const float*)d_in[6];
    const float* b3   = (const float*)d_in[7];
    const float* A    = (const float*)d_in[8];   // [Mm, NCODE]
    const float* leta = (const float*)d_in[9];
    const float* ltau = (const float*)d_in[10];
    const float* Psi  = (const float*)d_in[11];  // [NOUT, NCODE]
    const float* Mmat = (const float*)d_in[12];  // [Mm, NOUT]

    float* out     = (float*)d_out;
    float* o_ybg   = out;
    float* o_z     = o_ybg + (size_t)BATCH * NOUTD;
    float* o_alpha = o_z   + (size_t)BATCH * MMDIM;
    float* o_yhat  = o_alpha + (size_t)BATCH * NCODE;

    float *h1, *h2, *v, *a0, *a1;
    cudaGetSymbolAddress((void**)&h1, g_h1);
    cudaGetSymbolAddress((void**)&h2, g_h2);
    cudaGetSymbolAddress((void**)&v,  g_v);
    cudaGetSymbolAddress((void**)&a0, g_a0);
    cudaGetSymbolAddress((void**)&a1, g_a1);

    const dim3 blk(256);

    // ---- background MLP -----------------------------------------------------
    gemm128<EPI_GELU, false><<<dim3(H1DIM / 128, BATCH / 128), blk>>>(
        x, W1, h1, H1DIM, PDIM, b1, nullptr, nullptr, 0);
    gemm128<EPI_GELU, false><<<dim3(H2DIM / 128, BATCH / 128), blk>>>(
        h1, W2, h2, H2DIM, H1DIM, b2, nullptr, nullptr, 0);
    gemm128<EPI_BIAS, false><<<dim3(NOUTD / 128, BATCH / 128), blk>>>(
        h2, W3, o_ybg, NOUTD, H2DIM, b3, nullptr, nullptr, 0);

    // ---- z = b - y_bg @ M^T  (M stored [Mm, NOUT] => NT layout) -------------
    gemm128<EPI_ZSUB, true><<<dim3(MMDIM / 128, BATCH / 128), blk>>>(
        o_ybg, Mmat, o_z, MMDIM, NOUTD, bvec, nullptr, nullptr, 0);

    // ---- FISTA loop ----------------------------------------------------------
    const int n4 = (BATCH * NCODE) / 4;
    fill0_kernel<<<(n4 + 255) / 256, 256>>>((float4*)a0, n4);
    fill0_kernel<<<(n4 + 255) / 256, 256>>>((float4*)a1, n4);

    float t = 1.0f;
    float* aprev = a0;
    float* acur  = a1;
    for (int k = 0; k < KSTEPS; k++) {
        float beta = 0.0f;
        if (k > 0) {   // data-independent momentum recurrence (fp32, as in ref)
            float tn = 0.5f * (1.0f + sqrtf(1.0f + 4.0f * t * t));
            beta = (t - 1.0f) / tn;
            t = tn;
        }
        vcomb_kernel<<<(n4 + 255) / 256, 256>>>(
            (const float4*)acur, (const float4*)aprev, (float4*)v, beta, n4);

        // r = v @ A^T - z   (A [Mm, NCODE] => NT, N=Mm, K=NCODE); r lives in g_h2
        gemm128<EPI_RSUB, true><<<dim3(MMDIM / 128, BATCH / 128), blk>>>(
            v, A, h2, MMDIM, NCODE, o_z, nullptr, nullptr, 0);

        // alpha_new = soft(v - eta*(r @ A), eta*tau)   (NN, N=NCODE, K=Mm)
        float* dst = (k == KSTEPS - 1) ? o_alpha : aprev;
        gemm128<EPI_FISTA, false><<<dim3(NCODE / 128, BATCH / 128), blk>>>(
            h2, A, dst, NCODE, MMDIM, v, leta, ltau, k);

        aprev = acur;
        acur  = dst;
    }

    // ---- y_hat = y_bg + alpha @ Psi^T  (Psi [NOUT, NCODE] => NT) ------------
    gemm128<EPI_ADD, true><<<dim3(NOUTD / 128, BATCH / 128), blk>>>(
        o_alpha, Psi, o_yhat, NOUTD, NCODE, o_ybg, nullptr, nullptr, 0);
}